// round 1
// baseline (speedup 1.0000x reference)
#include <cuda_runtime.h>
#include <math.h>

// Problem constants
constexpr int B_   = 8192;
constexpr int NE_  = 20000;
constexpr int H_   = 512;
constexpr int C_   = 50;
constexpr int KIN_ = 25600;   // C_*H_

typedef unsigned long long ull;

// ---------------- scratch (static device memory; no allocations) -------------
__device__ float g_xs[(size_t)B_ * 3 * H_];       // gathered stacked input (B,3,H)
__device__ float g_part0[B_ * 6];                 // bn0 partials
__device__ float g_s0[3], g_t0[3];
__device__ float g_part1[B_ * 100];               // bn1 partials (sum[50], sq[50] per b)
__device__ float g_s1[C_], g_t1[C_];
__device__ float g_a[(size_t)B_ * KIN_];          // FC input A (B, C*H) — 839 MB
__device__ float g_fc[B_ * H_];                   // FC output (pre-bn2)
__device__ float g_part2[256 * 1024];             // bn2 partials
__device__ float g_s2[H_], g_t2[H_];
__device__ float g_z[B_ * H_];                    // relu(bn2(fc)) — score GEMM A

// ---------------- packed f32x2 helpers (sm_103a) ------------------------------
static __device__ __forceinline__ ull f2pack(float x, float y) {
    ull r;
    asm("mov.b64 %0, {%1, %2};" : "=l"(r) : "f"(x), "f"(y));
    return r;
}
static __device__ __forceinline__ void f2fma(ull& d, ull a, ull b) {
    asm("fma.rn.f32x2 %0, %1, %2, %0;" : "+l"(d) : "l"(a), "l"(b));
}

// ======================= K1: gather + bn0 partial stats ======================
__global__ void k_gather(const int* __restrict__ facts, const float* __restrict__ ent,
                         const float* __restrict__ rel, const float* __restrict__ erb)
{
    int b = blockIdx.x, t = threadIdx.x;
    int f0 = facts[b * 3 + 0];
    int f1 = facts[b * 3 + 1];
    const float* r0 = ent + (size_t)f0 * H_;
    const float* r1 = rel + (size_t)f1 * H_;
    const float* r2 = erb + (size_t)f0 * H_;
    float* xb = g_xs + (size_t)b * 3 * H_;

    float s[3] = {0.f, 0.f, 0.f}, q[3] = {0.f, 0.f, 0.f};
    for (int h = t; h < H_; h += 128) {
        float v0 = r0[h], v1 = r1[h], v2 = r2[h];
        xb[h] = v0; xb[H_ + h] = v1; xb[2 * H_ + h] = v2;
        s[0] += v0; q[0] += v0 * v0;
        s[1] += v1; q[1] += v1 * v1;
        s[2] += v2; q[2] += v2 * v2;
    }
    __shared__ float red[4][6];
    #pragma unroll
    for (int i = 0; i < 3; i++) {
        #pragma unroll
        for (int o = 16; o; o >>= 1) {
            s[i] += __shfl_xor_sync(0xffffffffu, s[i], o);
            q[i] += __shfl_xor_sync(0xffffffffu, q[i], o);
        }
    }
    int w = t >> 5, ln = t & 31;
    if (ln == 0) {
        #pragma unroll
        for (int i = 0; i < 3; i++) { red[w][i] = s[i]; red[w][3 + i] = q[i]; }
    }
    __syncthreads();
    if (t < 6) {
        float acc = red[0][t] + red[1][t] + red[2][t] + red[3][t];
        g_part0[b * 6 + t] = acc;
    }
}

// ======================= K2: finalize bn0 =====================================
__global__ void k_fin0(const float* __restrict__ gg, const float* __restrict__ bb)
{
    __shared__ double sd[256];
    __shared__ double tot[6];
    int t = threadIdx.x;
    for (int st = 0; st < 6; st++) {
        double a = 0.0;
        for (int j = t; j < B_; j += 256) a += (double)g_part0[j * 6 + st];
        sd[t] = a; __syncthreads();
        for (int o = 128; o; o >>= 1) { if (t < o) sd[t] += sd[t + o]; __syncthreads(); }
        if (t == 0) tot[st] = sd[0];
        __syncthreads();
    }
    if (t < 3) {
        double cnt  = (double)B_ * (double)H_;
        double mean = tot[t] / cnt;
        double var  = tot[3 + t] / cnt - mean * mean;
        double sc   = (double)gg[t] / sqrt(var + 1e-5);
        g_s0[t] = (float)sc;
        g_t0[t] = (float)((double)bb[t] - mean * sc);
    }
}

// ======================= K3: conv + bn1 partial stats =========================
__global__ void k_conv_stats(const float* __restrict__ cw, const float* __restrict__ cb)
{
    __shared__ float xn[3][514];
    __shared__ float w[450];
    __shared__ float cbs[C_];
    __shared__ float ssum[C_], ssq[C_];
    int b = blockIdx.x, t = threadIdx.x;

    for (int i = t; i < 450; i += 256) w[i] = cw[i];
    if (t < C_) { cbs[t] = cb[t]; ssum[t] = 0.f; ssq[t] = 0.f; }
    for (int i = t; i < 3 * H_; i += 256) {
        int ch = i >> 9, h = i & 511;
        xn[ch][h + 1] = g_xs[((size_t)b * 3 + ch) * H_ + h] * g_s0[ch] + g_t0[ch];
    }
    if (t < 3) { xn[t][0] = 0.f; xn[t][513] = 0.f; }
    __syncthreads();

    for (int c = 0; c < C_; c++) {
        float w0 = w[c*9+0], w1 = w[c*9+1], w2 = w[c*9+2];
        float w3 = w[c*9+3], w4 = w[c*9+4], w5 = w[c*9+5];
        float w6 = w[c*9+6], w7 = w[c*9+7], w8 = w[c*9+8];
        float bs = 0.f, bq = 0.f;
        #pragma unroll
        for (int hh = 0; hh < 2; hh++) {
            int h = t + hh * 256;
            float y = cbs[c]
                + w0 * xn[0][h] + w1 * xn[0][h + 1] + w2 * xn[0][h + 2]
                + w3 * xn[1][h] + w4 * xn[1][h + 1] + w5 * xn[1][h + 2]
                + w6 * xn[2][h] + w7 * xn[2][h + 1] + w8 * xn[2][h + 2];
            bs += y; bq += y * y;
        }
        #pragma unroll
        for (int o = 16; o; o >>= 1) {
            bs += __shfl_xor_sync(0xffffffffu, bs, o);
            bq += __shfl_xor_sync(0xffffffffu, bq, o);
        }
        if ((t & 31) == 0) { atomicAdd(&ssum[c], bs); atomicAdd(&ssq[c], bq); }
    }
    __syncthreads();
    if (t < C_) {
        g_part1[(size_t)b * 100 + t]       = ssum[t];
        g_part1[(size_t)b * 100 + 50 + t]  = ssq[t];
    }
}

// ======================= K4: finalize bn1 =====================================
__global__ void k_fin1(const float* __restrict__ gg, const float* __restrict__ bb)
{
    int c = blockIdx.x, t = threadIdx.x;
    __shared__ double sd[256];
    __shared__ double tS;
    double s = 0.0, q = 0.0;
    for (int j = t; j < B_; j += 256) {
        s += (double)g_part1[(size_t)j * 100 + c];
        q += (double)g_part1[(size_t)j * 100 + 50 + c];
    }
    sd[t] = s; __syncthreads();
    for (int o = 128; o; o >>= 1) { if (t < o) sd[t] += sd[t + o]; __syncthreads(); }
    if (t == 0) tS = sd[0];
    __syncthreads();
    sd[t] = q; __syncthreads();
    for (int o = 128; o; o >>= 1) { if (t < o) sd[t] += sd[t + o]; __syncthreads(); }
    if (t == 0) {
        double cnt  = (double)B_ * (double)H_;
        double mean = tS / cnt;
        double var  = sd[0] / cnt - mean * mean;
        double sc   = (double)gg[c] / sqrt(var + 1e-5);
        g_s1[c] = (float)sc;
        g_t1[c] = (float)((double)bb[c] - mean * sc);
    }
}

// ======================= K5: build A = relu(bn1(conv(xn))) ====================
__global__ void k_build(const float* __restrict__ cw, const float* __restrict__ cb)
{
    __shared__ float xn[3][514];
    __shared__ float w[450];
    __shared__ float cbs[C_];
    __shared__ float s1s[C_], t1s[C_];
    int b = blockIdx.x, t = threadIdx.x;

    for (int i = t; i < 450; i += 256) w[i] = cw[i];
    if (t < C_) { cbs[t] = cb[t]; s1s[t] = g_s1[t]; t1s[t] = g_t1[t]; }
    for (int i = t; i < 3 * H_; i += 256) {
        int ch = i >> 9, h = i & 511;
        xn[ch][h + 1] = g_xs[((size_t)b * 3 + ch) * H_ + h] * g_s0[ch] + g_t0[ch];
    }
    if (t < 3) { xn[t][0] = 0.f; xn[t][513] = 0.f; }
    __syncthreads();

    float* arow = g_a + (size_t)b * KIN_;
    for (int c = 0; c < C_; c++) {
        float w0 = w[c*9+0], w1 = w[c*9+1], w2 = w[c*9+2];
        float w3 = w[c*9+3], w4 = w[c*9+4], w5 = w[c*9+5];
        float w6 = w[c*9+6], w7 = w[c*9+7], w8 = w[c*9+8];
        float sc = s1s[c], tc = t1s[c], cbc = cbs[c];
        #pragma unroll
        for (int hh = 0; hh < 2; hh++) {
            int h = t + hh * 256;
            float y = cbc
                + w0 * xn[0][h] + w1 * xn[0][h + 1] + w2 * xn[0][h + 2]
                + w3 * xn[1][h] + w4 * xn[1][h + 1] + w5 * xn[1][h + 2]
                + w6 * xn[2][h] + w7 * xn[2][h + 1] + w8 * xn[2][h + 2];
            arow[c * H_ + h] = fmaxf(fmaf(y, sc, tc), 0.f);
        }
    }
}

// ======================= NT SGEMM with packed f32x2 FMA =======================
// C[m,n] = sum_k A[m,k]*Bm[n,k] (+ bias[n]); A: MxK row-major, Bm: NxK row-major.
// Tile 128x128x16, 256 threads, 8x8 per thread. M%128==0, K%16==0 assumed; N guarded.
#define GEMM_ROW(r, av) { ull ad = f2pack((av), (av));            \
    f2fma(acc[r][0], ad, bp0); f2fma(acc[r][1], ad, bp1);          \
    f2fma(acc[r][2], ad, bp2); f2fma(acc[r][3], ad, bp3); }

__global__ __launch_bounds__(256, 2)
void k_gemm_nt(const float* __restrict__ A, const float* __restrict__ Bm,
               float* __restrict__ Cm, int M, int N, int Kd,
               const float* __restrict__ bias)
{
    __shared__ float As[16][128];
    __shared__ float Bs[16][128];
    const int tid = threadIdx.x;
    const int mBase = blockIdx.y * 128;
    const int nBase = blockIdx.x * 128;
    const int lr = tid >> 2;          // 0..63
    const int lc = (tid & 3) << 2;    // 0,4,8,12
    const float* Ag0 = A + (size_t)(mBase + lr) * Kd + lc;
    const float* Ag1 = Ag0 + (size_t)64 * Kd;
    const int n0 = nBase + lr;
    const int n1 = n0 + 64;
    const float* Bg0 = Bm + (size_t)n0 * Kd + lc;
    const float* Bg1 = Bm + (size_t)n1 * Kd + lc;
    const bool v0 = (n0 < N), v1 = (n1 < N);
    const int tx = tid & 15, ty = tid >> 4;

    ull acc[8][4];
    #pragma unroll
    for (int i = 0; i < 8; i++) { acc[i][0] = 0; acc[i][1] = 0; acc[i][2] = 0; acc[i][3] = 0; }

    for (int kt = 0; kt < Kd; kt += 16) {
        float4 a0 = *(const float4*)(Ag0 + kt);
        float4 a1 = *(const float4*)(Ag1 + kt);
        float4 b0 = make_float4(0.f, 0.f, 0.f, 0.f);
        float4 b1 = make_float4(0.f, 0.f, 0.f, 0.f);
        if (v0) b0 = *(const float4*)(Bg0 + kt);
        if (v1) b1 = *(const float4*)(Bg1 + kt);

        As[lc + 0][lr] = a0.x; As[lc + 1][lr] = a0.y; As[lc + 2][lr] = a0.z; As[lc + 3][lr] = a0.w;
        As[lc + 0][lr + 64] = a1.x; As[lc + 1][lr + 64] = a1.y; As[lc + 2][lr + 64] = a1.z; As[lc + 3][lr + 64] = a1.w;
        Bs[lc + 0][lr] = b0.x; Bs[lc + 1][lr] = b0.y; Bs[lc + 2][lr] = b0.z; Bs[lc + 3][lr] = b0.w;
        Bs[lc + 0][lr + 64] = b1.x; Bs[lc + 1][lr + 64] = b1.y; Bs[lc + 2][lr + 64] = b1.z; Bs[lc + 3][lr + 64] = b1.w;
        __syncthreads();

        #pragma unroll
        for (int k = 0; k < 16; k++) {
            float4 af0 = *(const float4*)&As[k][ty << 2];
            float4 af1 = *(const float4*)&As[k][64 + (ty << 2)];
            ull bp0 = *(const ull*)&Bs[k][tx << 2];
            ull bp1 = *(const ull*)&Bs[k][(tx << 2) + 2];
            ull bp2 = *(const ull*)&Bs[k][64 + (tx << 2)];
            ull bp3 = *(const ull*)&Bs[k][66 + (tx << 2)];
            GEMM_ROW(0, af0.x) GEMM_ROW(1, af0.y) GEMM_ROW(2, af0.z) GEMM_ROW(3, af0.w)
            GEMM_ROW(4, af1.x) GEMM_ROW(5, af1.y) GEMM_ROW(6, af1.z) GEMM_ROW(7, af1.w)
        }
        __syncthreads();
    }

    #pragma unroll
    for (int i = 0; i < 8; i++) {
        int mloc = (i < 4) ? ((ty << 2) + i) : (64 + (ty << 2) + i - 4);
        float* crow = Cm + (size_t)(mBase + mloc) * N;
        #pragma unroll
        for (int p = 0; p < 4; p++) {
            int col = nBase + ((p < 2) ? ((tx << 2) + 2 * p) : (64 + (tx << 2) + 2 * (p - 2)));
            if (col < N) {
                float lo, hi;
                asm("mov.b64 {%0,%1}, %2;" : "=f"(lo), "=f"(hi) : "l"(acc[i][p]));
                if (bias) { lo += bias[col]; hi += bias[col + 1]; }
                float2 v; v.x = lo; v.y = hi;
                *(float2*)(crow + col) = v;
            }
        }
    }
}

// ======================= K7: bn2 partial stats ================================
__global__ void k_stats2_part()
{
    int blk = blockIdx.x;   // 256 blocks, 32 rows each
    int t = threadIdx.x;    // 256
    float s0 = 0.f, q0 = 0.f, s1 = 0.f, q1 = 0.f;
    int r0 = blk * 32;
    for (int r = 0; r < 32; r++) {
        const float* row = g_fc + (size_t)(r0 + r) * H_;
        float a = row[t];
        float b = row[t + 256];
        s0 += a; q0 += a * a;
        s1 += b; q1 += b * b;
    }
    g_part2[blk * 1024 + t]        = s0;
    g_part2[blk * 1024 + 256 + t]  = q0;
    g_part2[blk * 1024 + 512 + t]  = s1;
    g_part2[blk * 1024 + 768 + t]  = q1;
}

// ======================= K8: finalize bn2 =====================================
__global__ void k_fin2(const float* __restrict__ gg, const float* __restrict__ bb)
{
    int n = blockIdx.x * 256 + threadIdx.x;   // <<<2,256>>>
    int so = (n < 256) ? n : (256 + n);
    int qo = so + 256;
    double s = 0.0, q = 0.0;
    for (int j = 0; j < 256; j++) {
        s += (double)g_part2[j * 1024 + so];
        q += (double)g_part2[j * 1024 + qo];
    }
    double mean = s / (double)B_;
    double var  = q / (double)B_ - mean * mean;
    double sc   = (double)gg[n] / sqrt(var + 1e-5);
    g_s2[n] = (float)sc;
    g_t2[n] = (float)((double)bb[n] - mean * sc);
}

// ======================= K9: apply bn2 + relu =================================
__global__ void k_bn2relu()
{
    int idx = blockIdx.x * 256 + threadIdx.x;
    int n = idx & 511;
    g_z[idx] = fmaxf(fmaf(g_fc[idx], g_s2[n], g_t2[n]), 0.f);
}

// ======================= K11: row log_softmax (in place) ======================
__global__ void k_lsm(float* __restrict__ out)
{
    int b = blockIdx.x, t = threadIdx.x;
    float* p = out + (size_t)b * NE_;
    __shared__ float red[8];
    __shared__ float bc;

    float m = -3.0e38f;
    for (int i = t; i < NE_; i += 256) m = fmaxf(m, p[i]);
    #pragma unroll
    for (int o = 16; o; o >>= 1) m = fmaxf(m, __shfl_xor_sync(0xffffffffu, m, o));
    if ((t & 31) == 0) red[t >> 5] = m;
    __syncthreads();
    if (t == 0) { float v = red[0]; for (int j = 1; j < 8; j++) v = fmaxf(v, red[j]); bc = v; }
    __syncthreads();
    m = bc;

    float s = 0.f;
    for (int i = t; i < NE_; i += 256) s += __expf(p[i] - m);
    #pragma unroll
    for (int o = 16; o; o >>= 1) s += __shfl_xor_sync(0xffffffffu, s, o);
    __syncthreads();   // everyone has read bc before it is overwritten
    if ((t & 31) == 0) red[t >> 5] = s;
    __syncthreads();
    if (t == 0) { float v = 0.f; for (int j = 0; j < 8; j++) v += red[j]; bc = m + logf(v); }
    __syncthreads();
    float lse = bc;

    for (int i = t; i < NE_; i += 256) p[i] -= lse;
}

// ======================= launch ===============================================
extern "C" void kernel_launch(void* const* d_in, const int* in_sizes, int n_in,
                              void* d_out, int out_size)
{
    const int*   facts = (const int*)  d_in[0];
    const float* ent   = (const float*)d_in[1];
    const float* rel   = (const float*)d_in[2];
    const float* erb   = (const float*)d_in[3];
    const float* cw    = (const float*)d_in[4];
    const float* cb    = (const float*)d_in[5];
    const float* fcw   = (const float*)d_in[6];
    const float* fcb   = (const float*)d_in[7];
    const float* b0g   = (const float*)d_in[8];
    const float* b0b   = (const float*)d_in[9];
    const float* b1g   = (const float*)d_in[10];
    const float* b1b   = (const float*)d_in[11];
    const float* b2g   = (const float*)d_in[12];
    const float* b2b   = (const float*)d_in[13];
    float* out = (float*)d_out;

    float *p_a = nullptr, *p_fc = nullptr, *p_z = nullptr;
    cudaGetSymbolAddress((void**)&p_a,  g_a);
    cudaGetSymbolAddress((void**)&p_fc, g_fc);
    cudaGetSymbolAddress((void**)&p_z,  g_z);

    k_gather<<<B_, 128>>>(facts, ent, rel, erb);
    k_fin0<<<1, 256>>>(b0g, b0b);
    k_conv_stats<<<B_, 256>>>(cw, cb);
    k_fin1<<<C_, 256>>>(b1g, b1b);
    k_build<<<B_, 256>>>(cw, cb);

    // FC: (B, 25600) x (512, 25600)^T -> (B, 512)
    k_gemm_nt<<<dim3(512 / 128, B_ / 128), 256>>>(p_a, fcw, p_fc, B_, H_, KIN_, fcb);

    k_stats2_part<<<256, 256>>>();
    k_fin2<<<2, 256>>>(b2g, b2b);
    k_bn2relu<<<(B_ * H_) / 256, 256>>>();

    // score: (B, 512) x (20000, 512)^T -> (B, 20000)
    k_gemm_nt<<<dim3((NE_ + 127) / 128, B_ / 128), 256>>>(p_z, ent, out, B_, NE_, H_, nullptr);

    k_lsm<<<B_, 256>>>(out);
}

// round 3
// speedup vs baseline: 1.8325x; 1.8325x over previous
#include <cuda_runtime.h>
#include <cuda_bf16.h>
#include <math.h>

typedef unsigned int u32;
typedef unsigned long long u64;

// Problem constants
constexpr int B_    = 8192;
constexpr int NE_   = 20000;
constexpr int H_    = 512;
constexpr int C_    = 50;
constexpr int KIN_  = 25600;          // C_*H_
constexpr int KIN3_ = 3 * KIN_;       // 76800  (bf16x3 folded into K)
constexpr int H3_   = 3 * H_;         // 1536

// ---------------- scratch (static device memory; no allocations) -------------
__device__ float g_xs[(size_t)B_ * 3 * H_];
__device__ float g_part0[B_ * 6];
__device__ float g_s0[3], g_t0[3];
__device__ float g_part1[B_ * 100];
__device__ float g_s1[C_], g_t1[C_];
__device__ __nv_bfloat16 g_a3[(size_t)B_ * KIN3_];   // A' = [Ah|Al|Ah]  (1.26 GB)
__device__ __nv_bfloat16 g_w3[(size_t)H_ * KIN3_];   // W' = [Wh|Wh|Wl]
__device__ __nv_bfloat16 g_e3[(size_t)NE_ * H3_];    // E' = [Eh|Eh|El]
__device__ __nv_bfloat16 g_z3[(size_t)B_ * H3_];     // Z' = [Zh|Zl|Zh]
__device__ float g_fc[B_ * H_];
__device__ float g_part2[256 * 1024];
__device__ float g_s2[H_], g_t2[H_];

// ---------------- PTX helpers (portable: sm_80+ instructions only) -----------
static __device__ __forceinline__ u32 smem_u32(const void* p) {
    u32 a;
    asm("{ .reg .u64 t; cvta.to.shared.u64 t, %1; cvt.u32.u64 %0, t; }" : "=r"(a) : "l"(p));
    return a;
}

#define CP_ASYNC16(saddr, gptr, srcsz) \
    asm volatile("cp.async.cg.shared.global [%0], [%1], 16, %2;" \
                 :: "r"(saddr), "l"(gptr), "r"(srcsz) : "memory")
#define CP_COMMIT() asm volatile("cp.async.commit_group;" ::: "memory")

#define LDM_X4(r0, r1, r2, r3, addr) \
    asm volatile("ldmatrix.sync.aligned.m8n8.x4.shared.b16 {%0,%1,%2,%3}, [%4];" \
                 : "=r"(r0), "=r"(r1), "=r"(r2), "=r"(r3) : "r"(addr))

#define MMA16816(d, a, b0, b1) \
    asm volatile("mma.sync.aligned.m16n8k16.row.col.f32.bf16.bf16.f32 " \
                 "{%0,%1,%2,%3},{%4,%5,%6,%7},{%8,%9},{%0,%1,%2,%3};" \
                 : "+f"((d)[0]), "+f"((d)[1]), "+f"((d)[2]), "+f"((d)[3]) \
                 : "r"((a)[0]), "r"((a)[1]), "r"((a)[2]), "r"((a)[3]), \
                   "r"(b0), "r"(b1))

// ======================= K1: gather + bn0 partial stats ======================
__global__ void k_gather(const int* __restrict__ facts, const float* __restrict__ ent,
                         const float* __restrict__ rel, const float* __restrict__ erb)
{
    int b = blockIdx.x, t = threadIdx.x;
    int f0 = facts[b * 3 + 0];
    int f1 = facts[b * 3 + 1];
    const float* r0 = ent + (size_t)f0 * H_;
    const float* r1 = rel + (size_t)f1 * H_;
    const float* r2 = erb + (size_t)f0 * H_;
    float* xb = g_xs + (size_t)b * 3 * H_;

    float s[3] = {0.f, 0.f, 0.f}, q[3] = {0.f, 0.f, 0.f};
    for (int h = t; h < H_; h += 128) {
        float v0 = r0[h], v1 = r1[h], v2 = r2[h];
        xb[h] = v0; xb[H_ + h] = v1; xb[2 * H_ + h] = v2;
        s[0] += v0; q[0] += v0 * v0;
        s[1] += v1; q[1] += v1 * v1;
        s[2] += v2; q[2] += v2 * v2;
    }
    __shared__ float red[4][6];
    #pragma unroll
    for (int i = 0; i < 3; i++) {
        #pragma unroll
        for (int o = 16; o; o >>= 1) {
            s[i] += __shfl_xor_sync(0xffffffffu, s[i], o);
            q[i] += __shfl_xor_sync(0xffffffffu, q[i], o);
        }
    }
    int w = t >> 5, ln = t & 31;
    if (ln == 0) {
        #pragma unroll
        for (int i = 0; i < 3; i++) { red[w][i] = s[i]; red[w][3 + i] = q[i]; }
    }
    __syncthreads();
    if (t < 6) g_part0[b * 6 + t] = red[0][t] + red[1][t] + red[2][t] + red[3][t];
}

// ======================= K2: finalize bn0 =====================================
__global__ void k_fin0(const float* __restrict__ gg, const float* __restrict__ bb)
{
    __shared__ double sd[256];
    __shared__ double tot[6];
    int t = threadIdx.x;
    for (int st = 0; st < 6; st++) {
        double a = 0.0;
        for (int j = t; j < B_; j += 256) a += (double)g_part0[j * 6 + st];
        sd[t] = a; __syncthreads();
        for (int o = 128; o; o >>= 1) { if (t < o) sd[t] += sd[t + o]; __syncthreads(); }
        if (t == 0) tot[st] = sd[0];
        __syncthreads();
    }
    if (t < 3) {
        double cnt  = (double)B_ * (double)H_;
        double mean = tot[t] / cnt;
        double var  = tot[3 + t] / cnt - mean * mean;
        double sc   = (double)gg[t] / sqrt(var + 1e-5);
        g_s0[t] = (float)sc;
        g_t0[t] = (float)((double)bb[t] - mean * sc);
    }
}

// ======================= K3: conv + bn1 partial stats =========================
__global__ void k_conv_stats(const float* __restrict__ cw, const float* __restrict__ cb)
{
    __shared__ float xn[3][514];
    __shared__ float w[450];
    __shared__ float cbs[C_];
    __shared__ float ssum[C_], ssq[C_];
    int b = blockIdx.x, t = threadIdx.x;

    for (int i = t; i < 450; i += 256) w[i] = cw[i];
    if (t < C_) { cbs[t] = cb[t]; ssum[t] = 0.f; ssq[t] = 0.f; }
    for (int i = t; i < 3 * H_; i += 256) {
        int ch = i >> 9, h = i & 511;
        xn[ch][h + 1] = g_xs[((size_t)b * 3 + ch) * H_ + h] * g_s0[ch] + g_t0[ch];
    }
    if (t < 3) { xn[t][0] = 0.f; xn[t][513] = 0.f; }
    __syncthreads();

    for (int c = 0; c < C_; c++) {
        float w0 = w[c*9+0], w1 = w[c*9+1], w2 = w[c*9+2];
        float w3 = w[c*9+3], w4 = w[c*9+4], w5 = w[c*9+5];
        float w6 = w[c*9+6], w7 = w[c*9+7], w8 = w[c*9+8];
        float bs = 0.f, bq = 0.f;
        #pragma unroll
        for (int hh = 0; hh < 2; hh++) {
            int h = t + hh * 256;
            float y = cbs[c]
                + w0 * xn[0][h] + w1 * xn[0][h + 1] + w2 * xn[0][h + 2]
                + w3 * xn[1][h] + w4 * xn[1][h + 1] + w5 * xn[1][h + 2]
                + w6 * xn[2][h] + w7 * xn[2][h + 1] + w8 * xn[2][h + 2];
            bs += y; bq += y * y;
        }
        #pragma unroll
        for (int o = 16; o; o >>= 1) {
            bs += __shfl_xor_sync(0xffffffffu, bs, o);
            bq += __shfl_xor_sync(0xffffffffu, bq, o);
        }
        if ((t & 31) == 0) { atomicAdd(&ssum[c], bs); atomicAdd(&ssq[c], bq); }
    }
    __syncthreads();
    if (t < C_) {
        g_part1[(size_t)b * 100 + t]      = ssum[t];
        g_part1[(size_t)b * 100 + 50 + t] = ssq[t];
    }
}

// ======================= K4: finalize bn1 =====================================
__global__ void k_fin1(const float* __restrict__ gg, const float* __restrict__ bb)
{
    int c = blockIdx.x, t = threadIdx.x;
    __shared__ double sd[256];
    __shared__ double tS;
    double s = 0.0, q = 0.0;
    for (int j = t; j < B_; j += 256) {
        s += (double)g_part1[(size_t)j * 100 + c];
        q += (double)g_part1[(size_t)j * 100 + 50 + c];
    }
    sd[t] = s; __syncthreads();
    for (int o = 128; o; o >>= 1) { if (t < o) sd[t] += sd[t + o]; __syncthreads(); }
    if (t == 0) tS = sd[0];
    __syncthreads();
    sd[t] = q; __syncthreads();
    for (int o = 128; o; o >>= 1) { if (t < o) sd[t] += sd[t + o]; __syncthreads(); }
    if (t == 0) {
        double cnt  = (double)B_ * (double)H_;
        double mean = tS / cnt;
        double var  = sd[0] / cnt - mean * mean;
        double sc   = (double)gg[c] / sqrt(var + 1e-5);
        g_s1[c] = (float)sc;
        g_t1[c] = (float)((double)bb[c] - mean * sc);
    }
}

// ======================= K5: build A' = [Ah|Al|Ah] ===========================
__global__ void k_build(const float* __restrict__ cw, const float* __restrict__ cb)
{
    __shared__ float xn[3][514];
    __shared__ float w[450];
    __shared__ float cbs[C_];
    __shared__ float s1s[C_], t1s[C_];
    int b = blockIdx.x, t = threadIdx.x;

    for (int i = t; i < 450; i += 256) w[i] = cw[i];
    if (t < C_) { cbs[t] = cb[t]; s1s[t] = g_s1[t]; t1s[t] = g_t1[t]; }
    for (int i = t; i < 3 * H_; i += 256) {
        int ch = i >> 9, h = i & 511;
        xn[ch][h + 1] = g_xs[((size_t)b * 3 + ch) * H_ + h] * g_s0[ch] + g_t0[ch];
    }
    if (t < 3) { xn[t][0] = 0.f; xn[t][513] = 0.f; }
    __syncthreads();

    __nv_bfloat16* arow = g_a3 + (size_t)b * KIN3_;
    for (int c = 0; c < C_; c++) {
        float w0 = w[c*9+0], w1 = w[c*9+1], w2 = w[c*9+2];
        float w3 = w[c*9+3], w4 = w[c*9+4], w5 = w[c*9+5];
        float w6 = w[c*9+6], w7 = w[c*9+7], w8 = w[c*9+8];
        float sc = s1s[c], tc = t1s[c], cbc = cbs[c];
        #pragma unroll
        for (int hh = 0; hh < 2; hh++) {
            int h = t + hh * 256;
            float y = cbc
                + w0 * xn[0][h] + w1 * xn[0][h + 1] + w2 * xn[0][h + 2]
                + w3 * xn[1][h] + w4 * xn[1][h + 1] + w5 * xn[1][h + 2]
                + w6 * xn[2][h] + w7 * xn[2][h + 1] + w8 * xn[2][h + 2];
            float r = fmaxf(fmaf(y, sc, tc), 0.f);
            __nv_bfloat16 hi = __float2bfloat16(r);
            __nv_bfloat16 lo = __float2bfloat16(r - __bfloat162float(hi));
            int idx = c * H_ + h;
            arow[idx] = hi;
            arow[KIN_ + idx] = lo;
            arow[2 * KIN_ + idx] = hi;
        }
    }
}

// ======== splits: fp32 row-major (R,K) -> bf16 (R,3K) = [hi|hi|lo] ===========
__global__ void k_split_hhl(const float* __restrict__ src, __nv_bfloat16* __restrict__ dst,
                            int K, long long n)
{
    long long i = (long long)blockIdx.x * 256 + threadIdx.x;
    if (i < n) {
        int r = (int)(i / K), c = (int)(i % K);
        float x = src[i];
        __nv_bfloat16 h = __float2bfloat16(x);
        __nv_bfloat16 l = __float2bfloat16(x - __bfloat162float(h));
        __nv_bfloat16* d = dst + (size_t)r * 3 * K + c;
        d[0] = h; d[K] = h; d[2 * K] = l;
    }
}

// ======================= bf16 NT GEMM (mma.sync m16n8k16) ====================
// C[m,n] = sum_k A[m,k] * B[n,k].  A: MxK row-major bf16, B: NxK row-major bf16.
// Block 128x128, K-tile 64, 8 warps (2m x 4n) with 64x32 warp tiles.
// SMEM rows padded to 144 B (conflict-free ldmatrix). cp.async double buffer.
// Requires M%128==0, K%64==0; N%8==0 (guarded).
constexpr int RB = 144;                      // padded row bytes (64 bf16 + 8 pad)
constexpr int STG = 128 * RB;                // 18432 B per matrix per stage
constexpr int GEMM_SMEM = 4 * STG;           // A0,B0,A1,B1 = 73728 B

__global__ __launch_bounds__(256, 2)
void k_gemm(const __nv_bfloat16* __restrict__ A, const __nv_bfloat16* __restrict__ Bm,
            float* __restrict__ Cm, int N, int Kd, const float* __restrict__ bias)
{
    extern __shared__ char smem[];
    const u32 sb = smem_u32(smem);
    const int tid  = threadIdx.x;
    const int w    = tid >> 5, lane = tid & 31;
    const int mBase = blockIdx.x * 128;       // m in x: wave covers all m per n-panel
    const int nBase = blockIdx.y * 128;

    // per-thread cp.async geometry: 4 chunks (16B) each for A and B
    size_t gA[4]; u32 sA[4];
    size_t gB[4]; u32 sB[4]; u32 vB[4];
    #pragma unroll
    for (int i = 0; i < 4; i++) {
        int idx = tid + i * 256;              // 0..1023
        int r = idx >> 3, c = idx & 7;
        gA[i] = (size_t)(mBase + r) * Kd + c * 8;
        sA[i] = r * RB + c * 16;
        int n = nBase + r;
        int ok = (n < N);
        gB[i] = (size_t)(ok ? n : 0) * Kd + c * 8;
        sB[i] = r * RB + c * 16;
        vB[i] = ok ? 16u : 0u;
    }

    const int nT = Kd >> 6;

    // ldmatrix source addresses (per warp)
    const int wm = (w & 1) * 64;
    const int wn = (w >> 1) * 32;
    const u32 lrow = (lane & 15), lhalf = (lane >> 4) << 4;
    u32 aAddr[4], bAddr[2];
    #pragma unroll
    for (int i = 0; i < 4; i++) aAddr[i] = sb + (wm + i * 16 + lrow) * RB + lhalf;
    #pragma unroll
    for (int jj = 0; jj < 2; jj++) bAddr[jj] = sb + STG + (wn + jj * 16 + lrow) * RB + lhalf;

    float acc[4][4][4];
    #pragma unroll
    for (int i = 0; i < 4; i++)
        #pragma unroll
        for (int j = 0; j < 4; j++)
            #pragma unroll
            for (int q = 0; q < 4; q++) acc[i][j][q] = 0.f;

    // prologue: load tile 0 into stage 0
    {
        const u32 a0 = sb, b0 = sb + STG;
        #pragma unroll
        for (int i = 0; i < 4; i++) CP_ASYNC16(a0 + sA[i], A + gA[i], 16u);
        #pragma unroll
        for (int i = 0; i < 4; i++) CP_ASYNC16(b0 + sB[i], Bm + gB[i], vB[i]);
        CP_COMMIT();
    }

    for (int t = 0; t < nT; t++) {
        if (t + 1 < nT) {
            const u32 stoff = ((t + 1) & 1) * (2 * STG);
            const size_t ko = (size_t)(t + 1) * 64;
            #pragma unroll
            for (int i = 0; i < 4; i++) CP_ASYNC16(sb + stoff + sA[i], A + gA[i] + ko, 16u);
            #pragma unroll
            for (int i = 0; i < 4; i++) CP_ASYNC16(sb + stoff + STG + sB[i], Bm + gB[i] + ko, vB[i]);
            CP_COMMIT();
            asm volatile("cp.async.wait_group 1;" ::: "memory");
        } else {
            asm volatile("cp.async.wait_group 0;" ::: "memory");
        }
        __syncthreads();

        const u32 stoff = (t & 1) * (2 * STG);
        #pragma unroll
        for (int s = 0; s < 4; s++) {
            u32 ar[4][4], br[2][4];
            #pragma unroll
            for (int i = 0; i < 4; i++)
                LDM_X4(ar[i][0], ar[i][1], ar[i][2], ar[i][3], aAddr[i] + stoff + s * 32);
            #pragma unroll
            for (int jj = 0; jj < 2; jj++)
                LDM_X4(br[jj][0], br[jj][1], br[jj][2], br[jj][3], bAddr[jj] + stoff + s * 32);
            #pragma unroll
            for (int i = 0; i < 4; i++) {
                #pragma unroll
                for (int j = 0; j < 4; j++) {
                    MMA16816(acc[i][j], ar[i], br[j >> 1][j & 1], br[j >> 1][(j & 1) + 2]);
                }
            }
        }
        __syncthreads();
    }

    // epilogue
    const int mRow = mBase + wm + (lane >> 2);
    const int nCol = nBase + wn + ((lane & 3) << 1);
    #pragma unroll
    for (int i = 0; i < 4; i++) {
        #pragma unroll
        for (int j = 0; j < 4; j++) {
            int n = nCol + j * 8;
            if (n < N) {
                float bx = 0.f, by = 0.f;
                if (bias) { bx = bias[n]; by = bias[n + 1]; }
                int m0 = mRow + i * 16;
                float2 v0; v0.x = acc[i][j][0] + bx; v0.y = acc[i][j][1] + by;
                float2 v1; v1.x = acc[i][j][2] + bx; v1.y = acc[i][j][3] + by;
                *(float2*)(Cm + (size_t)m0 * N + n) = v0;
                *(float2*)(Cm + (size_t)(m0 + 8) * N + n) = v1;
            }
        }
    }
}

// ======================= K7: bn2 partial stats ================================
__global__ void k_stats2_part()
{
    int blk = blockIdx.x, t = threadIdx.x;
    float s0 = 0.f, q0 = 0.f, s1 = 0.f, q1 = 0.f;
    int r0 = blk * 32;
    for (int r = 0; r < 32; r++) {
        const float* row = g_fc + (size_t)(r0 + r) * H_;
        float a = row[t];
        float b = row[t + 256];
        s0 += a; q0 += a * a;
        s1 += b; q1 += b * b;
    }
    g_part2[blk * 1024 + t]       = s0;
    g_part2[blk * 1024 + 256 + t] = q0;
    g_part2[blk * 1024 + 512 + t] = s1;
    g_part2[blk * 1024 + 768 + t] = q1;
}

// ======================= K8: finalize bn2 =====================================
__global__ void k_fin2(const float* __restrict__ gg, const float* __restrict__ bb)
{
    int n = blockIdx.x * 256 + threadIdx.x;
    int so = (n < 256) ? n : (256 + n);
    int qo = so + 256;
    double s = 0.0, q = 0.0;
    for (int j = 0; j < 256; j++) {
        s += (double)g_part2[j * 1024 + so];
        q += (double)g_part2[j * 1024 + qo];
    }
    double mean = s / (double)B_;
    double var  = q / (double)B_ - mean * mean;
    double sc   = (double)gg[n] / sqrt(var + 1e-5);
    g_s2[n] = (float)sc;
    g_t2[n] = (float)((double)bb[n] - mean * sc);
}

// ======================= K9: bn2+relu -> Z' = [Zh|Zl|Zh] ======================
__global__ void k_bn2relu()
{
    int idx = blockIdx.x * 256 + threadIdx.x;     // over B_*H_
    int r = idx >> 9, c = idx & 511;
    float v = fmaxf(fmaf(g_fc[idx], g_s2[c], g_t2[c]), 0.f);
    __nv_bfloat16 h = __float2bfloat16(v);
    __nv_bfloat16 l = __float2bfloat16(v - __bfloat162float(h));
    __nv_bfloat16* d = g_z3 + (size_t)r * H3_ + c;
    d[0] = h; d[H_] = l; d[2 * H_] = h;
}

// ======================= K11: row log_softmax (in place) ======================
__global__ void k_lsm(float* __restrict__ out)
{
    int b = blockIdx.x, t = threadIdx.x;
    float* p = out + (size_t)b * NE_;
    __shared__ float red[8];
    __shared__ float bc;

    float m = -3.0e38f;
    for (int i = t; i < NE_; i += 256) m = fmaxf(m, p[i]);
    #pragma unroll
    for (int o = 16; o; o >>= 1) m = fmaxf(m, __shfl_xor_sync(0xffffffffu, m, o));
    if ((t & 31) == 0) red[t >> 5] = m;
    __syncthreads();
    if (t == 0) { float v = red[0]; for (int j = 1; j < 8; j++) v = fmaxf(v, red[j]); bc = v; }
    __syncthreads();
    m = bc;

    float s = 0.f;
    for (int i = t; i < NE_; i += 256) s += __expf(p[i] - m);
    #pragma unroll
    for (int o = 16; o; o >>= 1) s += __shfl_xor_sync(0xffffffffu, s, o);
    __syncthreads();
    if ((t & 31) == 0) red[t >> 5] = s;
    __syncthreads();
    if (t == 0) { float v = 0.f; for (int j = 0; j < 8; j++) v += red[j]; bc = m + logf(v); }
    __syncthreads();
    float lse = bc;

    for (int i = t; i < NE_; i += 256) p[i] -= lse;
}

// ======================= launch ===============================================
extern "C" void kernel_launch(void* const* d_in, const int* in_sizes, int n_in,
                              void* d_out, int out_size)
{
    const int*   facts = (const int*)  d_in[0];
    const float* ent   = (const float*)d_in[1];
    const float* rel   = (const float*)d_in[2];
    const float* erb   = (const float*)d_in[3];
    const float* cw    = (const float*)d_in[4];
    const float* cb    = (const float*)d_in[5];
    const float* fcw   = (const float*)d_in[6];
    const float* fcb   = (const float*)d_in[7];
    const float* b0g   = (const float*)d_in[8];
    const float* b0b   = (const float*)d_in[9];
    const float* b1g   = (const float*)d_in[10];
    const float* b1b   = (const float*)d_in[11];
    const float* b2g   = (const float*)d_in[12];
    const float* b2b   = (const float*)d_in[13];
    float* out = (float*)d_out;

    cudaFuncSetAttribute(k_gemm, cudaFuncAttributeMaxDynamicSharedMemorySize, GEMM_SMEM);

    __nv_bfloat16 *p_a3, *p_w3, *p_e3, *p_z3;
    float *p_fc;
    cudaGetSymbolAddress((void**)&p_a3, g_a3);
    cudaGetSymbolAddress((void**)&p_w3, g_w3);
    cudaGetSymbolAddress((void**)&p_e3, g_e3);
    cudaGetSymbolAddress((void**)&p_z3, g_z3);
    cudaGetSymbolAddress((void**)&p_fc, g_fc);

    k_gather<<<B_, 128>>>(facts, ent, rel, erb);
    k_fin0<<<1, 256>>>(b0g, b0b);
    k_conv_stats<<<B_, 256>>>(cw, cb);
    k_fin1<<<C_, 256>>>(b1g, b1b);
    k_build<<<B_, 256>>>(cw, cb);

    {
        long long nW = (long long)H_ * KIN_;
        k_split_hhl<<<(u32)((nW + 255) / 256), 256>>>(fcw, p_w3, KIN_, nW);
        long long nE = (long long)NE_ * H_;
        k_split_hhl<<<(u32)((nE + 255) / 256), 256>>>(ent, p_e3, H_, nE);
    }

    // FC: (8192, 76800) x (512, 76800)^T -> (8192, 512), + bias
    k_gemm<<<dim3(B_ / 128, H_ / 128), 256, GEMM_SMEM>>>(p_a3, p_w3, p_fc, H_, KIN3_, fcb);

    k_stats2_part<<<256, 256>>>();
    k_fin2<<<2, 256>>>(b2g, b2b);
    k_bn2relu<<<(B_ * H_) / 256, 256>>>();

    // score: (8192, 1536) x (20000, 1536)^T -> (8192, 20000)
    k_gemm<<<dim3(B_ / 128, (NE_ + 127) / 128), 256, GEMM_SMEM>>>(p_z3, p_e3, out, NE_, H3_, nullptr);

    k_lsm<<<B_, 256>>>(out);
}

// round 4
// speedup vs baseline: 3.7002x; 2.0192x over previous
#include <cuda_runtime.h>
#include <cuda_fp16.h>
#include <math.h>

typedef unsigned int u32;
typedef unsigned long long u64;

// Problem constants
constexpr int B_    = 8192;
constexpr int NE_   = 20000;
constexpr int H_    = 512;
constexpr int C_    = 50;
constexpr int KIN_  = 25600;          // C_*H_

// ---------------- scratch (static device memory; no allocations) -------------
__device__ float g_xs[(size_t)B_ * 3 * H_];
__device__ float g_part0[B_ * 6];
__device__ float g_s0[3], g_t0[3];
__device__ float g_part1[B_ * 100];
__device__ float g_s1[C_], g_t1[C_];
__device__ __half g_a16[(size_t)B_ * KIN_];    // A fp16 (420 MB)
__device__ __half g_w16[(size_t)H_ * KIN_];    // fc_w fp16
__device__ __half g_e16[(size_t)NE_ * H_];     // ent fp16
__device__ __half g_z16[(size_t)B_ * H_];      // z fp16
__device__ float g_fc[B_ * H_];
__device__ float g_part2[256 * 1024];
__device__ float g_s2[H_], g_t2[H_];

// ---------------- PTX helpers (portable: sm_80+ instructions only) -----------
static __device__ __forceinline__ u32 smem_u32(const void* p) {
    u32 a;
    asm("{ .reg .u64 t; cvta.to.shared.u64 t, %1; cvt.u32.u64 %0, t; }" : "=r"(a) : "l"(p));
    return a;
}

#define CP_ASYNC16(saddr, gptr, srcsz) \
    asm volatile("cp.async.cg.shared.global [%0], [%1], 16, %2;" \
                 :: "r"(saddr), "l"(gptr), "r"(srcsz) : "memory")
#define CP_COMMIT() asm volatile("cp.async.commit_group;" ::: "memory")

#define LDM_X4(r0, r1, r2, r3, addr) \
    asm volatile("ldmatrix.sync.aligned.m8n8.x4.shared.b16 {%0,%1,%2,%3}, [%4];" \
                 : "=r"(r0), "=r"(r1), "=r"(r2), "=r"(r3) : "r"(addr))

#define MMA16816(d, a, b0, b1) \
    asm volatile("mma.sync.aligned.m16n8k16.row.col.f32.f16.f16.f32 " \
                 "{%0,%1,%2,%3},{%4,%5,%6,%7},{%8,%9},{%0,%1,%2,%3};" \
                 : "+f"((d)[0]), "+f"((d)[1]), "+f"((d)[2]), "+f"((d)[3]) \
                 : "r"((a)[0]), "r"((a)[1]), "r"((a)[2]), "r"((a)[3]), \
                   "r"(b0), "r"(b1))

// ======================= K1: gather + bn0 partial stats ======================
__global__ void k_gather(const int* __restrict__ facts, const float* __restrict__ ent,
                         const float* __restrict__ rel, const float* __restrict__ erb)
{
    int b = blockIdx.x, t = threadIdx.x;
    int f0 = facts[b * 3 + 0];
    int f1 = facts[b * 3 + 1];
    const float* r0 = ent + (size_t)f0 * H_;
    const float* r1 = rel + (size_t)f1 * H_;
    const float* r2 = erb + (size_t)f0 * H_;
    float* xb = g_xs + (size_t)b * 3 * H_;

    float s[3] = {0.f, 0.f, 0.f}, q[3] = {0.f, 0.f, 0.f};
    for (int h = t; h < H_; h += 128) {
        float v0 = r0[h], v1 = r1[h], v2 = r2[h];
        xb[h] = v0; xb[H_ + h] = v1; xb[2 * H_ + h] = v2;
        s[0] += v0; q[0] += v0 * v0;
        s[1] += v1; q[1] += v1 * v1;
        s[2] += v2; q[2] += v2 * v2;
    }
    __shared__ float red[4][6];
    #pragma unroll
    for (int i = 0; i < 3; i++) {
        #pragma unroll
        for (int o = 16; o; o >>= 1) {
            s[i] += __shfl_xor_sync(0xffffffffu, s[i], o);
            q[i] += __shfl_xor_sync(0xffffffffu, q[i], o);
        }
    }
    int w = t >> 5, ln = t & 31;
    if (ln == 0) {
        #pragma unroll
        for (int i = 0; i < 3; i++) { red[w][i] = s[i]; red[w][3 + i] = q[i]; }
    }
    __syncthreads();
    if (t < 6) g_part0[b * 6 + t] = red[0][t] + red[1][t] + red[2][t] + red[3][t];
}

// ======================= K2: finalize bn0 =====================================
__global__ void k_fin0(const float* __restrict__ gg, const float* __restrict__ bb)
{
    __shared__ double sd[256];
    __shared__ double tot[6];
    int t = threadIdx.x;
    for (int st = 0; st < 6; st++) {
        double a = 0.0;
        for (int j = t; j < B_; j += 256) a += (double)g_part0[j * 6 + st];
        sd[t] = a; __syncthreads();
        for (int o = 128; o; o >>= 1) { if (t < o) sd[t] += sd[t + o]; __syncthreads(); }
        if (t == 0) tot[st] = sd[0];
        __syncthreads();
    }
    if (t < 3) {
        double cnt  = (double)B_ * (double)H_;
        double mean = tot[t] / cnt;
        double var  = tot[3 + t] / cnt - mean * mean;
        double sc   = (double)gg[t] / sqrt(var + 1e-5);
        g_s0[t] = (float)sc;
        g_t0[t] = (float)((double)bb[t] - mean * sc);
    }
}

// ======================= K3: conv + bn1 partial stats =========================
__global__ void k_conv_stats(const float* __restrict__ cw, const float* __restrict__ cb)
{
    __shared__ float xn[3][514];
    __shared__ float w[450];
    __shared__ float cbs[C_];
    __shared__ float ssum[C_], ssq[C_];
    int b = blockIdx.x, t = threadIdx.x;

    for (int i = t; i < 450; i += 256) w[i] = cw[i];
    if (t < C_) { cbs[t] = cb[t]; ssum[t] = 0.f; ssq[t] = 0.f; }
    for (int i = t; i < 3 * H_; i += 256) {
        int ch = i >> 9, h = i & 511;
        xn[ch][h + 1] = g_xs[((size_t)b * 3 + ch) * H_ + h] * g_s0[ch] + g_t0[ch];
    }
    if (t < 3) { xn[t][0] = 0.f; xn[t][513] = 0.f; }
    __syncthreads();

    for (int c = 0; c < C_; c++) {
        float w0 = w[c*9+0], w1 = w[c*9+1], w2 = w[c*9+2];
        float w3 = w[c*9+3], w4 = w[c*9+4], w5 = w[c*9+5];
        float w6 = w[c*9+6], w7 = w[c*9+7], w8 = w[c*9+8];
        float bs = 0.f, bq = 0.f;
        #pragma unroll
        for (int hh = 0; hh < 2; hh++) {
            int h = t + hh * 256;
            float y = cbs[c]
                + w0 * xn[0][h] + w1 * xn[0][h + 1] + w2 * xn[0][h + 2]
                + w3 * xn[1][h] + w4 * xn[1][h + 1] + w5 * xn[1][h + 2]
                + w6 * xn[2][h] + w7 * xn[2][h + 1] + w8 * xn[2][h + 2];
            bs += y; bq += y * y;
        }
        #pragma unroll
        for (int o = 16; o; o >>= 1) {
            bs += __shfl_xor_sync(0xffffffffu, bs, o);
            bq += __shfl_xor_sync(0xffffffffu, bq, o);
        }
        if ((t & 31) == 0) { atomicAdd(&ssum[c], bs); atomicAdd(&ssq[c], bq); }
    }
    __syncthreads();
    if (t < C_) {
        g_part1[(size_t)b * 100 + t]      = ssum[t];
        g_part1[(size_t)b * 100 + 50 + t] = ssq[t];
    }
}

// ======================= K4: finalize bn1 =====================================
__global__ void k_fin1(const float* __restrict__ gg, const float* __restrict__ bb)
{
    int c = blockIdx.x, t = threadIdx.x;
    __shared__ double sd[256];
    __shared__ double tS;
    double s = 0.0, q = 0.0;
    for (int j = t; j < B_; j += 256) {
        s += (double)g_part1[(size_t)j * 100 + c];
        q += (double)g_part1[(size_t)j * 100 + 50 + c];
    }
    sd[t] = s; __syncthreads();
    for (int o = 128; o; o >>= 1) { if (t < o) sd[t] += sd[t + o]; __syncthreads(); }
    if (t == 0) tS = sd[0];
    __syncthreads();
    sd[t] = q; __syncthreads();
    for (int o = 128; o; o >>= 1) { if (t < o) sd[t] += sd[t + o]; __syncthreads(); }
    if (t == 0) {
        double cnt  = (double)B_ * (double)H_;
        double mean = tS / cnt;
        double var  = sd[0] / cnt - mean * mean;
        double sc   = (double)gg[c] / sqrt(var + 1e-5);
        g_s1[c] = (float)sc;
        g_t1[c] = (float)((double)bb[c] - mean * sc);
    }
}

// ======================= K5: build A (fp16) ===================================
__global__ void k_build(const float* __restrict__ cw, const float* __restrict__ cb)
{
    __shared__ float xn[3][514];
    __shared__ float w[450];
    __shared__ float cbs[C_];
    __shared__ float s1s[C_], t1s[C_];
    int b = blockIdx.x, t = threadIdx.x;

    for (int i = t; i < 450; i += 256) w[i] = cw[i];
    if (t < C_) { cbs[t] = cb[t]; s1s[t] = g_s1[t]; t1s[t] = g_t1[t]; }
    for (int i = t; i < 3 * H_; i += 256) {
        int ch = i >> 9, h = i & 511;
        xn[ch][h + 1] = g_xs[((size_t)b * 3 + ch) * H_ + h] * g_s0[ch] + g_t0[ch];
    }
    if (t < 3) { xn[t][0] = 0.f; xn[t][513] = 0.f; }
    __syncthreads();

    __half* arow = g_a16 + (size_t)b * KIN_;
    for (int c = 0; c < C_; c++) {
        float w0 = w[c*9+0], w1 = w[c*9+1], w2 = w[c*9+2];
        float w3 = w[c*9+3], w4 = w[c*9+4], w5 = w[c*9+5];
        float w6 = w[c*9+6], w7 = w[c*9+7], w8 = w[c*9+8];
        float sc = s1s[c], tc = t1s[c], cbc = cbs[c];
        #pragma unroll
        for (int hh = 0; hh < 2; hh++) {
            int h = t + hh * 256;
            float y = cbc
                + w0 * xn[0][h] + w1 * xn[0][h + 1] + w2 * xn[0][h + 2]
                + w3 * xn[1][h] + w4 * xn[1][h + 1] + w5 * xn[1][h + 2]
                + w6 * xn[2][h] + w7 * xn[2][h + 1] + w8 * xn[2][h + 2];
            float r = fmaxf(fmaf(y, sc, tc), 0.f);
            arow[c * H_ + h] = __float2half_rn(r);
        }
    }
}

// ======================= split: fp32 -> fp16 ==================================
__global__ void k_cvt16(const float* __restrict__ src, __half* __restrict__ dst, long long n)
{
    long long i = (long long)blockIdx.x * 256 + threadIdx.x;
    if (i < n) dst[i] = __float2half_rn(src[i]);
}

// ======================= fp16 NT GEMM (mma.sync m16n8k16) ====================
// C[m,n] = sum_k A[m,k] * B[n,k].  A: MxK row-major fp16, B: NxK row-major fp16.
// Block 128x128, K-tile 64, 8 warps (2m x 4n) with 64x32 warp tiles.
// SMEM rows padded to 144 B (conflict-free ldmatrix). cp.async double buffer.
// Requires M%128==0, K%64==0; N%8==0 (guarded).
constexpr int RB = 144;                      // padded row bytes (64 fp16 + 8 pad)
constexpr int STG = 128 * RB;                // 18432 B per matrix per stage
constexpr int GEMM_SMEM = 4 * STG;           // A0,B0,A1,B1 = 73728 B

__global__ __launch_bounds__(256, 2)
void k_gemm(const __half* __restrict__ A, const __half* __restrict__ Bm,
            float* __restrict__ Cm, int N, int Kd, const float* __restrict__ bias)
{
    extern __shared__ char smem[];
    const u32 sb = smem_u32(smem);
    const int tid  = threadIdx.x;
    const int w    = tid >> 5, lane = tid & 31;
    const int mBase = blockIdx.x * 128;
    const int nBase = blockIdx.y * 128;

    // per-thread cp.async geometry: 4 chunks (16B) each for A and B
    size_t gA[4]; u32 sA[4];
    size_t gB[4]; u32 sB[4]; u32 vB[4];
    #pragma unroll
    for (int i = 0; i < 4; i++) {
        int idx = tid + i * 256;              // 0..1023
        int r = idx >> 3, c = idx & 7;
        gA[i] = (size_t)(mBase + r) * Kd + c * 8;
        sA[i] = r * RB + c * 16;
        int n = nBase + r;
        int ok = (n < N);
        gB[i] = (size_t)(ok ? n : 0) * Kd + c * 8;
        sB[i] = r * RB + c * 16;
        vB[i] = ok ? 16u : 0u;
    }

    const int nT = Kd >> 6;

    // ldmatrix source addresses (per warp)
    const int wm = (w & 1) * 64;
    const int wn = (w >> 1) * 32;
    const u32 lrow = (lane & 15), lhalf = (lane >> 4) << 4;
    u32 aAddr[4], bAddr[2];
    #pragma unroll
    for (int i = 0; i < 4; i++) aAddr[i] = sb + (wm + i * 16 + lrow) * RB + lhalf;
    #pragma unroll
    for (int jj = 0; jj < 2; jj++) bAddr[jj] = sb + STG + (wn + jj * 16 + lrow) * RB + lhalf;

    float acc[4][4][4];
    #pragma unroll
    for (int i = 0; i < 4; i++)
        #pragma unroll
        for (int j = 0; j < 4; j++)
            #pragma unroll
            for (int q = 0; q < 4; q++) acc[i][j][q] = 0.f;

    // prologue: load tile 0 into stage 0
    {
        const u32 a0 = sb, b0 = sb + STG;
        #pragma unroll
        for (int i = 0; i < 4; i++) CP_ASYNC16(a0 + sA[i], A + gA[i], 16u);
        #pragma unroll
        for (int i = 0; i < 4; i++) CP_ASYNC16(b0 + sB[i], Bm + gB[i], vB[i]);
        CP_COMMIT();
    }

    for (int t = 0; t < nT; t++) {
        if (t + 1 < nT) {
            const u32 stoff = ((t + 1) & 1) * (2 * STG);
            const size_t ko = (size_t)(t + 1) * 64;
            #pragma unroll
            for (int i = 0; i < 4; i++) CP_ASYNC16(sb + stoff + sA[i], A + gA[i] + ko, 16u);
            #pragma unroll
            for (int i = 0; i < 4; i++) CP_ASYNC16(sb + stoff + STG + sB[i], Bm + gB[i] + ko, vB[i]);
            CP_COMMIT();
            asm volatile("cp.async.wait_group 1;" ::: "memory");
        } else {
            asm volatile("cp.async.wait_group 0;" ::: "memory");
        }
        __syncthreads();

        const u32 stoff = (t & 1) * (2 * STG);
        #pragma unroll
        for (int s = 0; s < 4; s++) {
            u32 ar[4][4], br[2][4];
            #pragma unroll
            for (int i = 0; i < 4; i++)
                LDM_X4(ar[i][0], ar[i][1], ar[i][2], ar[i][3], aAddr[i] + stoff + s * 32);
            #pragma unroll
            for (int jj = 0; jj < 2; jj++)
                LDM_X4(br[jj][0], br[jj][1], br[jj][2], br[jj][3], bAddr[jj] + stoff + s * 32);
            #pragma unroll
            for (int i = 0; i < 4; i++) {
                #pragma unroll
                for (int j = 0; j < 4; j++) {
                    MMA16816(acc[i][j], ar[i], br[j >> 1][j & 1], br[j >> 1][(j & 1) + 2]);
                }
            }
        }
        __syncthreads();
    }

    // epilogue
    const int mRow = mBase + wm + (lane >> 2);
    const int nCol = nBase + wn + ((lane & 3) << 1);
    #pragma unroll
    for (int i = 0; i < 4; i++) {
        #pragma unroll
        for (int j = 0; j < 4; j++) {
            int n = nCol + j * 8;
            if (n < N) {
                float bx = 0.f, by = 0.f;
                if (bias) { bx = bias[n]; by = bias[n + 1]; }
                int m0 = mRow + i * 16;
                float2 v0; v0.x = acc[i][j][0] + bx; v0.y = acc[i][j][1] + by;
                float2 v1; v1.x = acc[i][j][2] + bx; v1.y = acc[i][j][3] + by;
                *(float2*)(Cm + (size_t)m0 * N + n) = v0;
                *(float2*)(Cm + (size_t)(m0 + 8) * N + n) = v1;
            }
        }
    }
}

// ======================= K7: bn2 partial stats ================================
__global__ void k_stats2_part()
{
    int blk = blockIdx.x, t = threadIdx.x;
    float s0 = 0.f, q0 = 0.f, s1 = 0.f, q1 = 0.f;
    int r0 = blk * 32;
    for (int r = 0; r < 32; r++) {
        const float* row = g_fc + (size_t)(r0 + r) * H_;
        float a = row[t];
        float b = row[t + 256];
        s0 += a; q0 += a * a;
        s1 += b; q1 += b * b;
    }
    g_part2[blk * 1024 + t]       = s0;
    g_part2[blk * 1024 + 256 + t] = q0;
    g_part2[blk * 1024 + 512 + t] = s1;
    g_part2[blk * 1024 + 768 + t] = q1;
}

// ======================= K8: finalize bn2 =====================================
__global__ void k_fin2(const float* __restrict__ gg, const float* __restrict__ bb)
{
    int n = blockIdx.x * 256 + threadIdx.x;
    int so = (n < 256) ? n : (256 + n);
    int qo = so + 256;
    double s = 0.0, q = 0.0;
    for (int j = 0; j < 256; j++) {
        s += (double)g_part2[j * 1024 + so];
        q += (double)g_part2[j * 1024 + qo];
    }
    double mean = s / (double)B_;
    double var  = q / (double)B_ - mean * mean;
    double sc   = (double)gg[n] / sqrt(var + 1e-5);
    g_s2[n] = (float)sc;
    g_t2[n] = (float)((double)bb[n] - mean * sc);
}

// ======================= K9: bn2+relu -> z fp16 ===============================
__global__ void k_bn2relu()
{
    int idx = blockIdx.x * 256 + threadIdx.x;     // over B_*H_
    int c = idx & 511;
    float v = fmaxf(fmaf(g_fc[idx], g_s2[c], g_t2[c]), 0.f);
    g_z16[idx] = __float2half_rn(v);
}

// ======================= K11: row log_softmax (in place) ======================
__global__ void k_lsm(float* __restrict__ out)
{
    int b = blockIdx.x, t = threadIdx.x;
    float* p = out + (size_t)b * NE_;
    __shared__ float red[8];
    __shared__ float bc;

    float m = -3.0e38f;
    for (int i = t; i < NE_; i += 256) m = fmaxf(m, p[i]);
    #pragma unroll
    for (int o = 16; o; o >>= 1) m = fmaxf(m, __shfl_xor_sync(0xffffffffu, m, o));
    if ((t & 31) == 0) red[t >> 5] = m;
    __syncthreads();
    if (t == 0) { float v = red[0]; for (int j = 1; j < 8; j++) v = fmaxf(v, red[j]); bc = v; }
    __syncthreads();
    m = bc;

    float s = 0.f;
    for (int i = t; i < NE_; i += 256) s += __expf(p[i] - m);
    #pragma unroll
    for (int o = 16; o; o >>= 1) s += __shfl_xor_sync(0xffffffffu, s, o);
    __syncthreads();
    if ((t & 31) == 0) red[t >> 5] = s;
    __syncthreads();
    if (t == 0) { float v = 0.f; for (int j = 0; j < 8; j++) v += red[j]; bc = m + logf(v); }
    __syncthreads();
    float lse = bc;

    for (int i = t; i < NE_; i += 256) p[i] -= lse;
}

// ======================= launch ===============================================
extern "C" void kernel_launch(void* const* d_in, const int* in_sizes, int n_in,
                              void* d_out, int out_size)
{
    const int*   facts = (const int*)  d_in[0];
    const float* ent   = (const float*)d_in[1];
    const float* rel   = (const float*)d_in[2];
    const float* erb   = (const float*)d_in[3];
    const float* cw    = (const float*)d_in[4];
    const float* cb    = (const float*)d_in[5];
    const float* fcw   = (const float*)d_in[6];
    const float* fcb   = (const float*)d_in[7];
    const float* b0g   = (const float*)d_in[8];
    const float* b0b   = (const float*)d_in[9];
    const float* b1g   = (const float*)d_in[10];
    const float* b1b   = (const float*)d_in[11];
    const float* b2g   = (const float*)d_in[12];
    const float* b2b   = (const float*)d_in[13];
    float* out = (float*)d_out;

    cudaFuncSetAttribute(k_gemm, cudaFuncAttributeMaxDynamicSharedMemorySize, GEMM_SMEM);

    __half *p_a16, *p_w16, *p_e16, *p_z16;
    float *p_fc;
    cudaGetSymbolAddress((void**)&p_a16, g_a16);
    cudaGetSymbolAddress((void**)&p_w16, g_w16);
    cudaGetSymbolAddress((void**)&p_e16, g_e16);
    cudaGetSymbolAddress((void**)&p_z16, g_z16);
    cudaGetSymbolAddress((void**)&p_fc,  g_fc);

    k_gather<<<B_, 128>>>(facts, ent, rel, erb);
    k_fin0<<<1, 256>>>(b0g, b0b);
    k_conv_stats<<<B_, 256>>>(cw, cb);
    k_fin1<<<C_, 256>>>(b1g, b1b);
    k_build<<<B_, 256>>>(cw, cb);

    {
        long long nW = (long long)H_ * KIN_;
        k_cvt16<<<(u32)((nW + 255) / 256), 256>>>(fcw, p_w16, nW);
        long long nE = (long long)NE_ * H_;
        k_cvt16<<<(u32)((nE + 255) / 256), 256>>>(ent, p_e16, nE);
    }

    // FC: (8192, 25600) x (512, 25600)^T -> (8192, 512), + bias
    k_gemm<<<dim3(B_ / 128, H_ / 128), 256, GEMM_SMEM>>>(p_a16, p_w16, p_fc, H_, KIN_, fcb);

    k_stats2_part<<<256, 256>>>();
    k_fin2<<<2, 256>>>(b2g, b2b);
    k_bn2relu<<<(B_ * H_) / 256, 256>>>();

    // score: (8192, 512) x (20000, 512)^T -> (8192, 20000)
    k_gemm<<<dim3(B_ / 128, (NE_ + 127) / 128), 256, GEMM_SMEM>>>(p_z16, p_e16, out, NE_, H_, nullptr);

    k_lsm<<<B_, 256>>>(out);
}

// round 5
// speedup vs baseline: 3.7431x; 1.0116x over previous
#include <cuda_runtime.h>
#include <cuda_fp16.h>
#include <math.h>

typedef unsigned int u32;
typedef unsigned long long u64;

// Problem constants
constexpr int B_    = 8192;
constexpr int NE_   = 20000;
constexpr int H_    = 512;
constexpr int C_    = 50;
constexpr int KIN_  = 25600;          // C_*H_

// ---------------- scratch (static device memory; no allocations) -------------
__device__ float g_xs[(size_t)B_ * 3 * H_];
__device__ float g_part0[B_ * 6];
__device__ float g_s0[3], g_t0[3];
__device__ float g_part1[B_ * 100];
__device__ float g_s1[C_], g_t1[C_];
__device__ __half g_a16[(size_t)B_ * KIN_];    // A fp16 (420 MB)
__device__ __half g_w16[(size_t)H_ * KIN_];    // fc_w fp16
__device__ __half g_e16[(size_t)NE_ * H_];     // ent fp16
__device__ __half g_z16[(size_t)B_ * H_];      // z fp16
__device__ float g_fc[B_ * H_];
__device__ float g_part2[256 * 1024];
__device__ float g_s2[H_], g_t2[H_];

// ---------------- PTX helpers (portable: sm_80+ instructions only) -----------
static __device__ __forceinline__ u32 smem_u32(const void* p) {
    u32 a;
    asm("{ .reg .u64 t; cvta.to.shared.u64 t, %1; cvt.u32.u64 %0, t; }" : "=r"(a) : "l"(p));
    return a;
}

#define CP_ASYNC16(saddr, gptr, srcsz) \
    asm volatile("cp.async.cg.shared.global [%0], [%1], 16, %2;" \
                 :: "r"(saddr), "l"(gptr), "r"(srcsz) : "memory")
#define CP_COMMIT() asm volatile("cp.async.commit_group;" ::: "memory")

#define LDM_X4(r0, r1, r2, r3, addr) \
    asm volatile("ldmatrix.sync.aligned.m8n8.x4.shared.b16 {%0,%1,%2,%3}, [%4];" \
                 : "=r"(r0), "=r"(r1), "=r"(r2), "=r"(r3) : "r"(addr))

#define MMA16816(d, a, b0, b1) \
    asm volatile("mma.sync.aligned.m16n8k16.row.col.f32.f16.f16.f32 " \
                 "{%0,%1,%2,%3},{%4,%5,%6,%7},{%8,%9},{%0,%1,%2,%3};" \
                 : "+f"((d)[0]), "+f"((d)[1]), "+f"((d)[2]), "+f"((d)[3]) \
                 : "r"((a)[0]), "r"((a)[1]), "r"((a)[2]), "r"((a)[3]), \
                   "r"(b0), "r"(b1))

// ======================= K1: gather + bn0 partial stats ======================
__global__ void k_gather(const int* __restrict__ facts, const float* __restrict__ ent,
                         const float* __restrict__ rel, const float* __restrict__ erb)
{
    int b = blockIdx.x, t = threadIdx.x;
    int f0 = facts[b * 3 + 0];
    int f1 = facts[b * 3 + 1];
    const float* r0 = ent + (size_t)f0 * H_;
    const float* r1 = rel + (size_t)f1 * H_;
    const float* r2 = erb + (size_t)f0 * H_;
    float* xb = g_xs + (size_t)b * 3 * H_;

    float s[3] = {0.f, 0.f, 0.f}, q[3] = {0.f, 0.f, 0.f};
    for (int h = t; h < H_; h += 128) {
        float v0 = r0[h], v1 = r1[h], v2 = r2[h];
        xb[h] = v0; xb[H_ + h] = v1; xb[2 * H_ + h] = v2;
        s[0] += v0; q[0] += v0 * v0;
        s[1] += v1; q[1] += v1 * v1;
        s[2] += v2; q[2] += v2 * v2;
    }
    __shared__ float red[4][6];
    #pragma unroll
    for (int i = 0; i < 3; i++) {
        #pragma unroll
        for (int o = 16; o; o >>= 1) {
            s[i] += __shfl_xor_sync(0xffffffffu, s[i], o);
            q[i] += __shfl_xor_sync(0xffffffffu, q[i], o);
        }
    }
    int w = t >> 5, ln = t & 31;
    if (ln == 0) {
        #pragma unroll
        for (int i = 0; i < 3; i++) { red[w][i] = s[i]; red[w][3 + i] = q[i]; }
    }
    __syncthreads();
    if (t < 6) g_part0[b * 6 + t] = red[0][t] + red[1][t] + red[2][t] + red[3][t];
}

// ======================= K2: finalize bn0 =====================================
__global__ void k_fin0(const float* __restrict__ gg, const float* __restrict__ bb)
{
    __shared__ double sd[256];
    __shared__ double tot[6];
    int t = threadIdx.x;
    for (int st = 0; st < 6; st++) {
        double a = 0.0;
        for (int j = t; j < B_; j += 256) a += (double)g_part0[j * 6 + st];
        sd[t] = a; __syncthreads();
        for (int o = 128; o; o >>= 1) { if (t < o) sd[t] += sd[t + o]; __syncthreads(); }
        if (t == 0) tot[st] = sd[0];
        __syncthreads();
    }
    if (t < 3) {
        double cnt  = (double)B_ * (double)H_;
        double mean = tot[t] / cnt;
        double var  = tot[3 + t] / cnt - mean * mean;
        double sc   = (double)gg[t] / sqrt(var + 1e-5);
        g_s0[t] = (float)sc;
        g_t0[t] = (float)((double)bb[t] - mean * sc);
    }
}

// ======================= K3: conv + bn1 partial stats =========================
__global__ void k_conv_stats(const float* __restrict__ cw, const float* __restrict__ cb)
{
    __shared__ float xn[3][514];
    __shared__ float w[450];
    __shared__ float cbs[C_];
    __shared__ float ssum[C_], ssq[C_];
    int b = blockIdx.x, t = threadIdx.x;

    for (int i = t; i < 450; i += 256) w[i] = cw[i];
    if (t < C_) { cbs[t] = cb[t]; ssum[t] = 0.f; ssq[t] = 0.f; }
    for (int i = t; i < 3 * H_; i += 256) {
        int ch = i >> 9, h = i & 511;
        xn[ch][h + 1] = g_xs[((size_t)b * 3 + ch) * H_ + h] * g_s0[ch] + g_t0[ch];
    }
    if (t < 3) { xn[t][0] = 0.f; xn[t][513] = 0.f; }
    __syncthreads();

    for (int c = 0; c < C_; c++) {
        float w0 = w[c*9+0], w1 = w[c*9+1], w2 = w[c*9+2];
        float w3 = w[c*9+3], w4 = w[c*9+4], w5 = w[c*9+5];
        float w6 = w[c*9+6], w7 = w[c*9+7], w8 = w[c*9+8];
        float bs = 0.f, bq = 0.f;
        #pragma unroll
        for (int hh = 0; hh < 2; hh++) {
            int h = t + hh * 256;
            float y = cbs[c]
                + w0 * xn[0][h] + w1 * xn[0][h + 1] + w2 * xn[0][h + 2]
                + w3 * xn[1][h] + w4 * xn[1][h + 1] + w5 * xn[1][h + 2]
                + w6 * xn[2][h] + w7 * xn[2][h + 1] + w8 * xn[2][h + 2];
            bs += y; bq += y * y;
        }
        #pragma unroll
        for (int o = 16; o; o >>= 1) {
            bs += __shfl_xor_sync(0xffffffffu, bs, o);
            bq += __shfl_xor_sync(0xffffffffu, bq, o);
        }
        if ((t & 31) == 0) { atomicAdd(&ssum[c], bs); atomicAdd(&ssq[c], bq); }
    }
    __syncthreads();
    if (t < C_) {
        g_part1[(size_t)b * 100 + t]      = ssum[t];
        g_part1[(size_t)b * 100 + 50 + t] = ssq[t];
    }
}

// ======================= K4: finalize bn1 =====================================
__global__ void k_fin1(const float* __restrict__ gg, const float* __restrict__ bb)
{
    int c = blockIdx.x, t = threadIdx.x;
    __shared__ double sd[256];
    __shared__ double tS;
    double s = 0.0, q = 0.0;
    for (int j = t; j < B_; j += 256) {
        s += (double)g_part1[(size_t)j * 100 + c];
        q += (double)g_part1[(size_t)j * 100 + 50 + c];
    }
    sd[t] = s; __syncthreads();
    for (int o = 128; o; o >>= 1) { if (t < o) sd[t] += sd[t + o]; __syncthreads(); }
    if (t == 0) tS = sd[0];
    __syncthreads();
    sd[t] = q; __syncthreads();
    for (int o = 128; o; o >>= 1) { if (t < o) sd[t] += sd[t + o]; __syncthreads(); }
    if (t == 0) {
        double cnt  = (double)B_ * (double)H_;
        double mean = tS / cnt;
        double var  = sd[0] / cnt - mean * mean;
        double sc   = (double)gg[c] / sqrt(var + 1e-5);
        g_s1[c] = (float)sc;
        g_t1[c] = (float)((double)bb[c] - mean * sc);
    }
}

// ======================= K5: build A (fp16) ===================================
__global__ void k_build(const float* __restrict__ cw, const float* __restrict__ cb)
{
    __shared__ float xn[3][514];
    __shared__ float w[450];
    __shared__ float cbs[C_];
    __shared__ float s1s[C_], t1s[C_];
    int b = blockIdx.x, t = threadIdx.x;

    for (int i = t; i < 450; i += 256) w[i] = cw[i];
    if (t < C_) { cbs[t] = cb[t]; s1s[t] = g_s1[t]; t1s[t] = g_t1[t]; }
    for (int i = t; i < 3 * H_; i += 256) {
        int ch = i >> 9, h = i & 511;
        xn[ch][h + 1] = g_xs[((size_t)b * 3 + ch) * H_ + h] * g_s0[ch] + g_t0[ch];
    }
    if (t < 3) { xn[t][0] = 0.f; xn[t][513] = 0.f; }
    __syncthreads();

    __half* arow = g_a16 + (size_t)b * KIN_;
    for (int c = 0; c < C_; c++) {
        float w0 = w[c*9+0], w1 = w[c*9+1], w2 = w[c*9+2];
        float w3 = w[c*9+3], w4 = w[c*9+4], w5 = w[c*9+5];
        float w6 = w[c*9+6], w7 = w[c*9+7], w8 = w[c*9+8];
        float sc = s1s[c], tc = t1s[c], cbc = cbs[c];
        #pragma unroll
        for (int hh = 0; hh < 2; hh++) {
            int h = t + hh * 256;
            float y = cbc
                + w0 * xn[0][h] + w1 * xn[0][h + 1] + w2 * xn[0][h + 2]
                + w3 * xn[1][h] + w4 * xn[1][h + 1] + w5 * xn[1][h + 2]
                + w6 * xn[2][h] + w7 * xn[2][h + 1] + w8 * xn[2][h + 2];
            float r = fmaxf(fmaf(y, sc, tc), 0.f);
            arow[c * H_ + h] = __float2half_rn(r);
        }
    }
}

// ======================= split: fp32 -> fp16 ==================================
__global__ void k_cvt16(const float* __restrict__ src, __half* __restrict__ dst, long long n)
{
    long long i = (long long)blockIdx.x * 256 + threadIdx.x;
    if (i < n) dst[i] = __float2half_rn(src[i]);
}

// ======================= fp16 NT GEMM (mma.sync m16n8k16) ====================
// C[m,n] = sum_k A[m,k] * B[n,k].  A: MxK row-major fp16, B: NxK row-major fp16.
// Block 128x128, K-tile 64, 8 warps (2m x 4n) with 64x32 warp tiles.
// 3-stage cp.async pipeline, ONE __syncthreads per K-tile.
// SMEM rows padded to 144 B (conflict-free ldmatrix).
// Requires M%128==0, K%64==0; N%8==0 (guarded).
constexpr int RB   = 144;                    // padded row bytes (64 fp16 + 8 pad)
constexpr int ASZ  = 128 * RB;               // 18432 B (A or B tile)
constexpr int STG  = 2 * ASZ;                // 36864 B per stage (A + B)
constexpr int NSTG = 3;
constexpr int GEMM_SMEM = NSTG * STG;        // 110592 B

__global__ __launch_bounds__(256, 2)
void k_gemm(const __half* __restrict__ A, const __half* __restrict__ Bm,
            float* __restrict__ Cm, int N, int Kd, const float* __restrict__ bias)
{
    extern __shared__ char smem[];
    const u32 sb = smem_u32(smem);
    const int tid  = threadIdx.x;
    const int w    = tid >> 5, lane = tid & 31;
    const int mBase = blockIdx.x * 128;
    const int nBase = blockIdx.y * 128;

    // per-thread cp.async geometry: 4 chunks (16B) each for A and B
    size_t gA[4]; u32 sA[4];
    size_t gB[4]; u32 sB[4]; u32 vB[4];
    #pragma unroll
    for (int i = 0; i < 4; i++) {
        int idx = tid + i * 256;              // 0..1023
        int r = idx >> 3, c = idx & 7;
        gA[i] = (size_t)(mBase + r) * Kd + c * 8;
        sA[i] = r * RB + c * 16;
        int n = nBase + r;
        int ok = (n < N);
        gB[i] = (size_t)(ok ? n : 0) * Kd + c * 8;
        sB[i] = r * RB + c * 16;
        vB[i] = ok ? 16u : 0u;
    }

    const int nT = Kd >> 6;

    // ldmatrix source addresses (per warp), relative to stage base
    const int wm = (w & 1) * 64;
    const int wn = (w >> 1) * 32;
    const u32 lrow = (lane & 15), lhalf = (lane >> 4) << 4;
    u32 aRel[4], bRel[2];
    #pragma unroll
    for (int i = 0; i < 4; i++) aRel[i] = (wm + i * 16 + lrow) * RB + lhalf;
    #pragma unroll
    for (int jj = 0; jj < 2; jj++) bRel[jj] = ASZ + (wn + jj * 16 + lrow) * RB + lhalf;

    float acc[4][4][4];
    #pragma unroll
    for (int i = 0; i < 4; i++)
        #pragma unroll
        for (int j = 0; j < 4; j++)
            #pragma unroll
            for (int q = 0; q < 4; q++) acc[i][j][q] = 0.f;

    // prologue: stages 0..NSTG-2
    #pragma unroll
    for (int p = 0; p < NSTG - 1; p++) {
        if (p < nT) {
            const u32 st = sb + p * STG;
            const size_t ko = (size_t)p * 64;
            #pragma unroll
            for (int i = 0; i < 4; i++) CP_ASYNC16(st + sA[i], A + gA[i] + ko, 16u);
            #pragma unroll
            for (int i = 0; i < 4; i++) CP_ASYNC16(st + ASZ + sB[i], Bm + gB[i] + ko, vB[i]);
        }
        CP_COMMIT();
    }

    for (int t = 0; t < nT; t++) {
        asm volatile("cp.async.wait_group 1;" ::: "memory");
        __syncthreads();

        // issue K-tile t+NSTG-1 into its stage (empty commit keeps ledger uniform)
        {
            int nt = t + NSTG - 1;
            if (nt < nT) {
                const u32 st = sb + (nt % NSTG) * STG;
                const size_t ko = (size_t)nt * 64;
                #pragma unroll
                for (int i = 0; i < 4; i++) CP_ASYNC16(st + sA[i], A + gA[i] + ko, 16u);
                #pragma unroll
                for (int i = 0; i < 4; i++) CP_ASYNC16(st + ASZ + sB[i], Bm + gB[i] + ko, vB[i]);
            }
            CP_COMMIT();
        }

        const u32 stoff = sb + (t % NSTG) * STG;
        #pragma unroll
        for (int s = 0; s < 4; s++) {
            u32 ar[4][4], br[2][4];
            #pragma unroll
            for (int i = 0; i < 4; i++)
                LDM_X4(ar[i][0], ar[i][1], ar[i][2], ar[i][3], stoff + aRel[i] + s * 32);
            #pragma unroll
            for (int jj = 0; jj < 2; jj++)
                LDM_X4(br[jj][0], br[jj][1], br[jj][2], br[jj][3], stoff + bRel[jj] + s * 32);
            #pragma unroll
            for (int i = 0; i < 4; i++) {
                #pragma unroll
                for (int j = 0; j < 4; j++) {
                    MMA16816(acc[i][j], ar[i], br[j >> 1][j & 1], br[j >> 1][(j & 1) + 2]);
                }
            }
        }
    }

    // epilogue
    const int mRow = mBase + wm + (lane >> 2);
    const int nCol = nBase + wn + ((lane & 3) << 1);
    #pragma unroll
    for (int i = 0; i < 4; i++) {
        #pragma unroll
        for (int j = 0; j < 4; j++) {
            int n = nCol + j * 8;
            if (n < N) {
                float bx = 0.f, by = 0.f;
                if (bias) { bx = bias[n]; by = bias[n + 1]; }
                int m0 = mRow + i * 16;
                float2 v0; v0.x = acc[i][j][0] + bx; v0.y = acc[i][j][1] + by;
                float2 v1; v1.x = acc[i][j][2] + bx; v1.y = acc[i][j][3] + by;
                *(float2*)(Cm + (size_t)m0 * N + n) = v0;
                *(float2*)(Cm + (size_t)(m0 + 8) * N + n) = v1;
            }
        }
    }
}

// ======================= K7: bn2 partial stats ================================
__global__ void k_stats2_part()
{
    int blk = blockIdx.x, t = threadIdx.x;
    float s0 = 0.f, q0 = 0.f, s1 = 0.f, q1 = 0.f;
    int r0 = blk * 32;
    for (int r = 0; r < 32; r++) {
        const float* row = g_fc + (size_t)(r0 + r) * H_;
        float a = row[t];
        float b = row[t + 256];
        s0 += a; q0 += a * a;
        s1 += b; q1 += b * b;
    }
    g_part2[blk * 1024 + t]       = s0;
    g_part2[blk * 1024 + 256 + t] = q0;
    g_part2[blk * 1024 + 512 + t] = s1;
    g_part2[blk * 1024 + 768 + t] = q1;
}

// ======================= K8: finalize bn2 =====================================
__global__ void k_fin2(const float* __restrict__ gg, const float* __restrict__ bb)
{
    int n = blockIdx.x * 256 + threadIdx.x;
    int so = (n < 256) ? n : (256 + n);
    int qo = so + 256;
    double s = 0.0, q = 0.0;
    for (int j = 0; j < 256; j++) {
        s += (double)g_part2[j * 1024 + so];
        q += (double)g_part2[j * 1024 + qo];
    }
    double mean = s / (double)B_;
    double var  = q / (double)B_ - mean * mean;
    double sc   = (double)gg[n] / sqrt(var + 1e-5);
    g_s2[n] = (float)sc;
    g_t2[n] = (float)((double)bb[n] - mean * sc);
}

// ======================= K9: bn2+relu -> z fp16 ===============================
__global__ void k_bn2relu()
{
    int idx = blockIdx.x * 256 + threadIdx.x;     // over B_*H_
    int c = idx & 511;
    float v = fmaxf(fmaf(g_fc[idx], g_s2[c], g_t2[c]), 0.f);
    g_z16[idx] = __float2half_rn(v);
}

// ======================= K11: row log_softmax (online, 2 passes) ==============
__global__ void k_lsm(float* __restrict__ out)
{
    int b = blockIdx.x, t = threadIdx.x;
    float* p = out + (size_t)b * NE_;
    __shared__ float rm[8], rs[8];
    __shared__ float lseS;

    float m = -3.0e38f, s = 0.f;
    for (int i = t; i < NE_; i += 256) {
        float v = p[i];
        if (v > m) { s = s * __expf(m - v) + 1.f; m = v; }
        else       { s += __expf(v - m); }
    }
    #pragma unroll
    for (int o = 16; o; o >>= 1) {
        float mo = __shfl_xor_sync(0xffffffffu, m, o);
        float so = __shfl_xor_sync(0xffffffffu, s, o);
        float M = fmaxf(m, mo);
        s = s * __expf(m - M) + so * __expf(mo - M);
        m = M;
    }
    if ((t & 31) == 0) { rm[t >> 5] = m; rs[t >> 5] = s; }
    __syncthreads();
    if (t == 0) {
        float M = rm[0], S = rs[0];
        for (int j = 1; j < 8; j++) {
            float M2 = fmaxf(M, rm[j]);
            S = S * __expf(M - M2) + rs[j] * __expf(rm[j] - M2);
            M = M2;
        }
        lseS = M + logf(S);
    }
    __syncthreads();
    float lse = lseS;
    for (int i = t; i < NE_; i += 256) p[i] -= lse;
}

// ======================= launch ===============================================
extern "C" void kernel_launch(void* const* d_in, const int* in_sizes, int n_in,
                              void* d_out, int out_size)
{
    const int*   facts = (const int*)  d_in[0];
    const float* ent   = (const float*)d_in[1];
    const float* rel   = (const float*)d_in[2];
    const float* erb   = (const float*)d_in[3];
    const float* cw    = (const float*)d_in[4];
    const float* cb    = (const float*)d_in[5];
    const float* fcw   = (const float*)d_in[6];
    const float* fcb   = (const float*)d_in[7];
    const float* b0g   = (const float*)d_in[8];
    const float* b0b   = (const float*)d_in[9];
    const float* b1g   = (const float*)d_in[10];
    const float* b1b   = (const float*)d_in[11];
    const float* b2g   = (const float*)d_in[12];
    const float* b2b   = (const float*)d_in[13];
    float* out = (float*)d_out;

    cudaFuncSetAttribute(k_gemm, cudaFuncAttributeMaxDynamicSharedMemorySize, GEMM_SMEM);

    __half *p_a16, *p_w16, *p_e16, *p_z16;
    float *p_fc;
    cudaGetSymbolAddress((void**)&p_a16, g_a16);
    cudaGetSymbolAddress((void**)&p_w16, g_w16);
    cudaGetSymbolAddress((void**)&p_e16, g_e16);
    cudaGetSymbolAddress((void**)&p_z16, g_z16);
    cudaGetSymbolAddress((void**)&p_fc,  g_fc);

    k_gather<<<B_, 128>>>(facts, ent, rel, erb);
    k_fin0<<<1, 256>>>(b0g, b0b);
    k_conv_stats<<<B_, 256>>>(cw, cb);
    k_fin1<<<C_, 256>>>(b1g, b1b);
    k_build<<<B_, 256>>>(cw, cb);

    {
        long long nW = (long long)H_ * KIN_;
        k_cvt16<<<(u32)((nW + 255) / 256), 256>>>(fcw, p_w16, nW);
        long long nE = (long long)NE_ * H_;
        k_cvt16<<<(u32)((nE + 255) / 256), 256>>>(ent, p_e16, nE);
    }

    // FC: (8192, 25600) x (512, 25600)^T -> (8192, 512), + bias
    k_gemm<<<dim3(B_ / 128, H_ / 128), 256, GEMM_SMEM>>>(p_a16, p_w16, p_fc, H_, KIN_, fcb);

    k_stats2_part<<<256, 256>>>();
    k_fin2<<<2, 256>>>(b2g, b2b);
    k_bn2relu<<<(B_ * H_) / 256, 256>>>();

    // score: (8192, 512) x (20000, 512)^T -> (8192, 20000)
    k_gemm<<<dim3(B_ / 128, (NE_ + 127) / 128), 256, GEMM_SMEM>>>(p_z16, p_e16, out, NE_, H_, nullptr);

    k_lsm<<<B_, 256>>>(out);
}